// round 10
// baseline (speedup 1.0000x reference)
#include <cuda_runtime.h>
#include <cuda_bf16.h>
#include <cstdint>

#define HID     128
#define KDIM    256
#define TILE    64
#define THREADS 256
#define NWARP   8
#define KPITCH  264
#define ROWB    (KPITCH * 2)   // 528 B row pitch

// ---- SMEM layout (bytes) ----
#define SM_B1   0
#define SM_W2   512
#define SM_RED  1536                           // 64 edges x 8 warps x float2 = 4096
#define SM_WHI  8192
#define SM_WLO  (SM_WHI + HID * ROWB)          // + 67584
#define SM_XHI  (SM_WLO + HID * ROWB)          // + 67584
#define SM_XLO  (SM_XHI + TILE * ROWB)         // + 33792
#define SMEM_BYTES (SM_XLO + TILE * ROWB)      // 210944 B

#define MMA_BF16(c, a0, a1, a2, a3, b0, b1) \
    asm volatile("mma.sync.aligned.m16n8k16.row.col.f32.bf16.bf16.f32 " \
        "{%0,%1,%2,%3}, {%4,%5,%6,%7}, {%8,%9}, {%0,%1,%2,%3};" \
        : "+f"((c)[0]), "+f"((c)[1]), "+f"((c)[2]), "+f"((c)[3]) \
        : "r"(a0), "r"(a1), "r"(a2), "r"(a3), "r"(b0), "r"(b1))

#define LDSM_X4(r0, r1, r2, r3, a) \
    asm volatile("ldmatrix.sync.aligned.m8n8.x4.shared.b16 {%0,%1,%2,%3}, [%4];" \
        : "=r"(r0), "=r"(r1), "=r"(r2), "=r"(r3) : "r"(a))
#define LDSM_X2(r0, r1, a) \
    asm volatile("ldmatrix.sync.aligned.m8n8.x2.shared.b16 {%0,%1}, [%2];" \
        : "=r"(r0), "=r"(r1) : "r"(a))

static __device__ __forceinline__ uint32_t smem_u32(const void* p) {
    uint32_t a;
    asm("{ .reg .u64 t; cvta.to.shared.u64 t, %1; cvt.u32.u64 %0, t; }" : "=r"(a) : "l"(p));
    return a;
}
static __device__ __forceinline__ uint32_t packbf(float e0, float e1) {
    union { ushort2 s; uint32_t u; } u;
    u.s.x = __bfloat16_as_ushort(__float2bfloat16(e0));
    u.s.y = __bfloat16_as_ushort(__float2bfloat16(e1));
    return u.u;
}
static __device__ __forceinline__ float bfres(float x) {
    return x - __bfloat162float(__float2bfloat16(x));
}

__global__ void __launch_bounds__(THREADS, 1)
edge_mlp_mma(const float* __restrict__ node_emb,
             const void*  __restrict__ edge_index,
             const float* __restrict__ W1,
             const float* __restrict__ b1,
             const float* __restrict__ W2,
             const float* __restrict__ b2,
             float* __restrict__ out,
             int E)
{
    extern __shared__ char smem[];
    float*  sB1  = (float*)(smem + SM_B1);
    float*  sW2  = (float*)(smem + SM_W2);
    float2* sRed = (float2*)(smem + SM_RED);   // [edge][warp]
    const uint32_t sbase = smem_u32(smem);

    const int tid  = threadIdx.x;
    const int warp = tid >> 5;      // warp owns features [16*warp, 16*warp+16)
    const int lane = tid & 31;
    const int g    = lane >> 2;
    const int t    = lane & 3;

    // ---- one-time staging: b1, W2, W1^T hi/lo ----
    for (int i = tid; i < HID;     i += THREADS) sB1[i] = __ldg(b1 + i);
    for (int i = tid; i < 2 * HID; i += THREADS) sW2[i] = __ldg(W2 + i);
    const float b2x = __ldg(b2), b2y = __ldg(b2 + 1);

    for (int i = tid; i < KDIM * HID; i += THREADS) {
        int k = i >> 7, n = i & 127;           // W1[k][n], coalesced
        float f = __ldg(W1 + i);
        __nv_bfloat16 h = __float2bfloat16(f);
        *(__nv_bfloat16*)(smem + SM_WHI + n * ROWB + k * 2) = h;
        *(__nv_bfloat16*)(smem + SM_WLO + n * ROWB + k * 2) =
            __float2bfloat16(f - __bfloat162float(h));
    }

    // edge_index dtype sniff (int64 idx < 1e5 -> high words zero)
    bool is64 = true;
    const unsigned* uwp = (const unsigned*)edge_index;
    #pragma unroll
    for (int i = 0; i < 16; i++) is64 = is64 && (uwp[2 * i + 1] == 0u);
    const long long* idx64 = (const long long*)edge_index;
    const int*       idx32 = (const int*)edge_index;

    __syncthreads();

    // ---- load this warp's B fragments into registers (persist whole kernel) ----
    // nt_global = 2*warp + j ; fragment (kt, j) from W^T rows [nt*8, nt*8+8)
    const uint32_t bHiB = sbase + SM_WHI + (uint32_t)(lane & 7) * ROWB
                        + (uint32_t)((lane >> 3) & 1) * 16;
    const uint32_t bLoB = bHiB + (uint32_t)(SM_WLO - SM_WHI);
    uint32_t bh[16][2][2], bl[16][2][2];
    #pragma unroll
    for (int kt = 0; kt < 16; kt++)
        #pragma unroll
        for (int j = 0; j < 2; j++) {
            const uint32_t bo = (uint32_t)(2 * warp + j) * (8u * ROWB) + (uint32_t)kt * 32u;
            LDSM_X2(bh[kt][j][0], bh[kt][j][1], bHiB + bo);
            LDSM_X2(bl[kt][j][0], bl[kt][j][1], bLoB + bo);
        }

    // A fragment base: row = edge-in-tile (mt*16 + lane&15)
    const uint32_t aHiB = sbase + SM_XHI + (uint32_t)(lane & 15) * ROWB
                        + (uint32_t)(lane >> 4) * 16;
    const uint32_t aLoB = aHiB + (uint32_t)(SM_XLO - SM_XHI);

    const int nTiles = (E + TILE - 1) / TILE;
    float2* out2 = (float2*)out;

    for (int tile = blockIdx.x; tile < nTiles; tile += gridDim.x) {
        const int e0 = tile * TILE;

        __syncthreads();   // previous tile's X/sRed reads done before overwrite

        // ---- gather: 4 threads per edge (half x chunk), bf16 hi/lo split ----
        {
            const int el = tid >> 2, half = (tid >> 1) & 1, ch = tid & 1;
            const int e  = e0 + el;
            int node = 0;
            if (e < E) {
                if (is64) node = (int)idx64[half ? (size_t)E + e : (size_t)e];
                else      node = idx32[half ? (size_t)E + e : (size_t)e];
            }
            const float4* src = (const float4*)(node_emb + (size_t)node * HID) + ch * 16;
            uint32_t* dh = (uint32_t*)(smem + SM_XHI) + el * (ROWB / 4) + half * 64 + ch * 32;
            uint32_t* dl = (uint32_t*)(smem + SM_XLO) + el * (ROWB / 4) + half * 64 + ch * 32;
            #pragma unroll 4
            for (int j = 0; j < 16; j++) {
                float4 v = __ldg(src + j);
                dh[2 * j]     = packbf(__bfloat162float(__float2bfloat16(v.x)),
                                       __bfloat162float(__float2bfloat16(v.y)));
                dh[2 * j + 1] = packbf(__bfloat162float(__float2bfloat16(v.z)),
                                       __bfloat162float(__float2bfloat16(v.w)));
                dl[2 * j]     = packbf(bfres(v.x), bfres(v.y));
                dl[2 * j + 1] = packbf(bfres(v.z), bfres(v.w));
            }
        }
        __syncthreads();

        // ---- per warp: 4 m-tiles x (16 kt) x (2 nt x 3 terms) ----
        #pragma unroll
        for (int mt = 0; mt < 4; mt++) {
            float acc[2][4];
            #pragma unroll
            for (int j = 0; j < 2; j++)
                #pragma unroll
                for (int c = 0; c < 4; c++) acc[j][c] = 0.f;

            const uint32_t aH = aHiB + (uint32_t)mt * (16u * ROWB);
            const uint32_t aL = aLoB + (uint32_t)mt * (16u * ROWB);
            #pragma unroll
            for (int kt = 0; kt < 16; kt++) {
                uint32_t ah0, ah1, ah2, ah3, al0, al1, al2, al3;
                LDSM_X4(ah0, ah1, ah2, ah3, aH + (uint32_t)kt * 32u);
                LDSM_X4(al0, al1, al2, al3, aL + (uint32_t)kt * 32u);
                #pragma unroll
                for (int j = 0; j < 2; j++) {
                    MMA_BF16(acc[j], ah0, ah1, ah2, ah3, bh[kt][j][0], bh[kt][j][1]);
                    MMA_BF16(acc[j], al0, al1, al2, al3, bh[kt][j][0], bh[kt][j][1]);
                    MMA_BF16(acc[j], ah0, ah1, ah2, ah3, bl[kt][j][0], bl[kt][j][1]);
                }
            }

            // epilogue for this m-tile: +b1, ReLU, xW2 partial over 16 features
            float p0a = 0.f, p1a = 0.f, p0b = 0.f, p1b = 0.f;
            #pragma unroll
            for (int j = 0; j < 2; j++)
                #pragma unroll
                for (int c = 0; c < 2; c++) {
                    const int f = (2 * warp + j) * 8 + t * 2 + c;
                    const float w20 = sW2[2 * f], w21 = sW2[2 * f + 1], bb = sB1[f];
                    float ha = fmaxf(acc[j][c]     + bb, 0.f);
                    float hb = fmaxf(acc[j][c + 2] + bb, 0.f);
                    p0a = fmaf(ha, w20, p0a);  p1a = fmaf(ha, w21, p1a);
                    p0b = fmaf(hb, w20, p0b);  p1b = fmaf(hb, w21, p1b);
                }
            #pragma unroll
            for (int off = 1; off <= 2; off <<= 1) {
                p0a += __shfl_xor_sync(0xffffffffu, p0a, off);
                p1a += __shfl_xor_sync(0xffffffffu, p1a, off);
                p0b += __shfl_xor_sync(0xffffffffu, p0b, off);
                p1b += __shfl_xor_sync(0xffffffffu, p1b, off);
            }
            if (t == 0) {
                sRed[(mt * 16 + g)     * NWARP + warp] = make_float2(p0a, p1a);
                sRed[(mt * 16 + g + 8) * NWARP + warp] = make_float2(p0b, p1b);
            }
        }
        __syncthreads();

        // ---- cross-warp reduce (8 partials per edge) + write ----
        if (tid < TILE) {
            const int e = e0 + tid;
            float2 s = make_float2(b2x, b2y);
            #pragma unroll
            for (int w = 0; w < NWARP; w++) {
                float2 v = sRed[tid * NWARP + w];
                s.x += v.x; s.y += v.y;
            }
            if (e < E) out2[e] = s;
        }
    }
}

extern "C" void kernel_launch(void* const* d_in, const int* in_sizes, int n_in,
                              void* d_out, int out_size) {
    const float* node_emb   = (const float*)d_in[0];
    const void*  edge_index = d_in[1];
    const float* W1         = (const float*)d_in[2];
    const float* b1         = (const float*)d_in[3];
    const float* W2         = (const float*)d_in[4];
    const float* b2         = (const float*)d_in[5];
    (void)in_sizes; (void)n_in;

    const int E = out_size / 2;
    const int nTiles = (E + TILE - 1) / TILE;

    cudaFuncSetAttribute(edge_mlp_mma,
                         cudaFuncAttributeMaxDynamicSharedMemorySize, SMEM_BYTES);

    int dev = 0, sms = 148;
    cudaGetDevice(&dev);
    cudaDeviceGetAttribute(&sms, cudaDevAttrMultiProcessorCount, dev);
    int grid = sms < nTiles ? sms : nTiles;

    edge_mlp_mma<<<grid, THREADS, SMEM_BYTES>>>(
        node_emb, edge_index, W1, b1, W2, b2, (float*)d_out, E);
}